// round 16
// baseline (speedup 1.0000x reference)
#include <cuda_runtime.h>
#include <cstdint>

typedef unsigned long long u64;

#define NB 8
#define WD 96
#define HD 96
#define CD 256
#define PBATCH (WD*HD)            /* 9216 */
#define BOFF (PBATCH*CD)          /* 2359296 floats per batch */
#define ARRN (NB*BOFF)            /* 18874368 */
#define NSPLIT 64
#define KSPLIT 384                /* 24576 / NSPLIT, multiple of 32 */

// ---------------- device scratch ----------------
__device__ float g_z[ARRN];                   // z = G x, p-major [b][w][h][c]
__device__ float g_v[ARRN];                   // v, p-major
__device__ float g_Sp[NSPLIT * 16 * PBATCH];  // [split][mode*8+b][96][96]
__device__ float g_P[16 * PBATCH];            // softmaxed probs
__device__ float g_wchi[512 * 256];           // [G ; Wv] hi (tf32)
__device__ float g_wclo[512 * 256];           // [G ; Wv] lo residual (tf32)
__device__ float g_u[256];                    // Wq^T bk
__device__ float g_u2[256];                   // Wk^T bq
__device__ float g_corr[2 * 768];             // [Cms ; Cma] col corrections

// ---------------- f32x2 helpers ----------------
__device__ __forceinline__ void ffma2(u64 &d, u64 a, u64 b) {
    asm("fma.rn.f32x2 %0, %1, %2, %0;" : "+l"(d) : "l"(a), "l"(b));
}
__device__ __forceinline__ u64 dup2(float x) {
    u64 r; asm("mov.b64 %0, {%1, %1};" : "=l"(r) : "f"(x)); return r;
}
__device__ __forceinline__ float2 unpack2(u64 v) {
    float2 f; asm("mov.b64 {%0, %1}, %2;" : "=f"(f.x), "=f"(f.y) : "l"(v)); return f;
}

// ---------------- tf32 mma helpers ----------------
__device__ __forceinline__ uint32_t tf32cvt(float x) {
    uint32_t u; asm("cvt.rna.tf32.f32 %0, %1;" : "=r"(u) : "f"(x)); return u;
}
__device__ __forceinline__ float tf32f(float x) {
    return __uint_as_float(tf32cvt(x));
}
__device__ __forceinline__ void mma1688(float* c, const uint32_t* a, const uint32_t* b) {
    asm volatile("mma.sync.aligned.m16n8k8.row.col.f32.tf32.tf32.f32 "
        "{%0,%1,%2,%3}, {%4,%5,%6,%7}, {%8,%9}, {%0,%1,%2,%3};"
        : "+f"(c[0]), "+f"(c[1]), "+f"(c[2]), "+f"(c[3])
        : "r"(a[0]), "r"(a[1]), "r"(a[2]), "r"(a[3]), "r"(b[0]), "r"(b[1]));
}

// ============================================================================
// Kernel 0: prep. Blocks 0..255: G row -> hi/lo split. 256..511: Wv -> hi/lo.
// Block 512: u. Block 513: u2.
// ============================================================================
__global__ __launch_bounds__(256) void prep_kernel(
    const float* __restrict__ W, const float* __restrict__ bias)
{
    const int blk = blockIdx.x;
    const int c = threadIdx.x;
    if (blk < 256) {
        __shared__ float sWq[256];
        sWq[c] = W[c * 256 + blk];          // Wq[t=c][o=blk]
        __syncthreads();
        float acc = 0.f;
#pragma unroll 4
        for (int t = 0; t < 256; t++)
            acc += sWq[t] * W[(256 + t) * 256 + c];   // Wk[t][c]
        float hi = tf32f(acc);
        g_wchi[blk * 256 + c] = hi;
        g_wclo[blk * 256 + c] = tf32f(acc - hi);
    } else if (blk < 512) {
        int o = blk - 256;
        float wv = W[(512 + o) * 256 + c];
        float hi = tf32f(wv);
        g_wchi[(256 + o) * 256 + c] = hi;
        g_wclo[(256 + o) * 256 + c] = tf32f(wv - hi);
    } else if (blk == 512) {
        float acc = 0.f;
#pragma unroll 4
        for (int t = 0; t < 256; t++)
            acc += W[t * 256 + c] * bias[256 + t];
        g_u[c] = acc;
    } else {
        float acc = 0.f;
#pragma unroll 4
        for (int t = 0; t < 256; t++)
            acc += W[(256 + t) * 256 + c] * bias[t];
        g_u2[c] = acc;
    }
}

// ============================================================================
// Kernel 1: main GEMM on tensor cores (tf32 split).
// z half (n0<256): 3 passes. v half: 2 passes.
// Grid (8 n-blocks, 576 m-blocks): n fastest -> X tile L2-reused, W resident.
// NOW occupancy 3 (launch_bounds caps regs at ~85; smem 3x61440 <= 228KB).
// ============================================================================
#define GT_STR 20
#define GT_A   (128 * GT_STR)
#define GT_B   (64 * GT_STR)
#define GT_SMEM (2 * (2 * GT_A + 2 * GT_B) * 4)   /* 61440 B */

__global__ __launch_bounds__(256, 3) void gemm_kernel(
    const float* __restrict__ X, const float* __restrict__ bias)
{
    extern __shared__ __align__(16) uint32_t gts[];
    uint32_t* Ahi = gts;
    uint32_t* Alo = gts + 2 * GT_A;
    uint32_t* Bhi = gts + 4 * GT_A;
    uint32_t* Blo = gts + 4 * GT_A + 2 * GT_B;

    const int tid  = threadIdx.x;
    const int lane = tid & 31, wid = tid >> 5;
    const int wm = wid & 3, wn = wid >> 2;
    const int n0 = blockIdx.x * 64;
    const int m0 = blockIdx.y * 128;
    const int isv = (n0 >= 256);

    const float* Ag  = X      + (size_t)m0 * CD;
    const float* Bgh = g_wchi + (size_t)n0 * CD;
    const float* Bgl = g_wclo + (size_t)n0 * CD;

    const int srow = tid >> 2;
    const int c4   = tid & 3;

    float acc[2][4][4];
#pragma unroll
    for (int tm = 0; tm < 2; tm++)
#pragma unroll
        for (int tn = 0; tn < 4; tn++)
#pragma unroll
            for (int q = 0; q < 4; q++) acc[tm][tn][q] = 0.f;

    float4 ra[2], rbh, rbl;
    ra[0] = *(const float4*)(Ag + (size_t)srow * CD + c4 * 4);
    ra[1] = *(const float4*)(Ag + (size_t)(srow + 64) * CD + c4 * 4);
    rbh   = *(const float4*)(Bgh + (size_t)srow * CD + c4 * 4);
    if (!isv) rbl = *(const float4*)(Bgl + (size_t)srow * CD + c4 * 4);
    {
#pragma unroll
        for (int it = 0; it < 2; it++) {
            const float* pa = (const float*)&ra[it];
            uint4 h, l;
            uint32_t* hp = (uint32_t*)&h; uint32_t* lp = (uint32_t*)&l;
#pragma unroll
            for (int u = 0; u < 4; u++) {
                uint32_t hb = tf32cvt(pa[u]);
                hp[u] = hb;
                lp[u] = tf32cvt(pa[u] - __uint_as_float(hb));
            }
            int off = (srow + 64 * it) * GT_STR + c4 * 4;
            *(uint4*)&Ahi[off] = h;
            *(uint4*)&Alo[off] = l;
        }
        int off = srow * GT_STR + c4 * 4;
        *(uint4*)&Bhi[off] = *(const uint4*)&rbh;
        if (!isv) *(uint4*)&Blo[off] = *(const uint4*)&rbl;
    }
    __syncthreads();

#pragma unroll 1
    for (int s = 0; s < 16; s++) {
        const int buf = s & 1;
        if (s < 15) {
            int ks = (s + 1) * 16;
            ra[0] = *(const float4*)(Ag + (size_t)srow * CD + ks + c4 * 4);
            ra[1] = *(const float4*)(Ag + (size_t)(srow + 64) * CD + ks + c4 * 4);
            rbh   = *(const float4*)(Bgh + (size_t)srow * CD + ks + c4 * 4);
            if (!isv) rbl = *(const float4*)(Bgl + (size_t)srow * CD + ks + c4 * 4);
        }
        const uint32_t* Abh = Ahi + buf * GT_A;
        const uint32_t* Abl = Alo + buf * GT_A;
        const uint32_t* Bbh = Bhi + buf * GT_B;
        const uint32_t* Bbl = Blo + buf * GT_B;
#pragma unroll
        for (int g = 0; g < 2; g++) {
            uint32_t ah[2][4], al[2][4];
#pragma unroll
            for (int tm = 0; tm < 2; tm++)
#pragma unroll
                for (int q = 0; q < 4; q++) {
                    int r = 32 * wm + 16 * tm + (lane >> 2) + 8 * (q & 1);
                    int c = 8 * g + (lane & 3) + 4 * (q >> 1);
                    ah[tm][q] = Abh[r * GT_STR + c];
                    al[tm][q] = Abl[r * GT_STR + c];
                }
            uint32_t bh[4][2], bl[4][2];
#pragma unroll
            for (int tn = 0; tn < 4; tn++)
#pragma unroll
                for (int q = 0; q < 2; q++) {
                    int n = 32 * wn + 8 * tn + (lane >> 2);
                    int k = 8 * g + (lane & 3) + 4 * q;
                    bh[tn][q] = Bbh[n * GT_STR + k];
                    if (!isv) bl[tn][q] = Bbl[n * GT_STR + k];
                }
#pragma unroll
            for (int tm = 0; tm < 2; tm++)
#pragma unroll
                for (int tn = 0; tn < 4; tn++) {
                    mma1688(acc[tm][tn], ah[tm], bh[tn]);
                    mma1688(acc[tm][tn], al[tm], bh[tn]);
                    if (!isv) mma1688(acc[tm][tn], ah[tm], bl[tn]);
                }
        }
        if (s < 15) {
            const int nbuf = buf ^ 1;
            uint32_t* Anh = Ahi + nbuf * GT_A;
            uint32_t* Anl = Alo + nbuf * GT_A;
#pragma unroll
            for (int it = 0; it < 2; it++) {
                const float* pa = (const float*)&ra[it];
                uint4 h, l;
                uint32_t* hp = (uint32_t*)&h; uint32_t* lp = (uint32_t*)&l;
#pragma unroll
                for (int u = 0; u < 4; u++) {
                    uint32_t hb = tf32cvt(pa[u]);
                    hp[u] = hb;
                    lp[u] = tf32cvt(pa[u] - __uint_as_float(hb));
                }
                int off = (srow + 64 * it) * GT_STR + c4 * 4;
                *(uint4*)&Anh[off] = h;
                *(uint4*)&Anl[off] = l;
            }
            int off = srow * GT_STR + c4 * 4;
            *(uint4*)&Bhi[nbuf * GT_B + off] = *(const uint4*)&rbh;
            if (!isv) *(uint4*)&Blo[nbuf * GT_B + off] = *(const uint4*)&rbl;
            __syncthreads();
        }
    }

    // epilogue: p-major store; bias only for v half
    const int cbase = n0 & 255;
    float* dst = isv ? g_v : g_z;
#pragma unroll
    for (int tm = 0; tm < 2; tm++)
#pragma unroll
        for (int tn = 0; tn < 4; tn++)
#pragma unroll
            for (int half = 0; half < 2; half++) {
                int p  = m0 + 32 * wm + 16 * tm + (lane >> 2) + 8 * half;
                int cl = cbase + 32 * wn + 8 * tn + 2 * (lane & 3);
                float2 r = make_float2(acc[tm][tn][2 * half], acc[tm][tn][2 * half + 1]);
                if (isv) {
                    float2 bv = *(const float2*)(bias + 512 + cl);
                    r.x += bv.x; r.y += bv.y;
                }
                *(float2*)(dst + (size_t)p * CD + cl) = r;
            }
}

// ============================================================================
// Kernel 1b: column corrections. (unchanged)
// ============================================================================
__global__ __launch_bounds__(256) void corr_kernel(const float* __restrict__ X)
{
    __shared__ float red[256];
    const int id = blockIdx.x;
    const int which = id / 768;
    const int r = id - which * 768;
    const int b = r / 96, idx = r - b * 96;
    const int c = threadIdx.x;

    const float uv = which ? g_u[c] : g_u2[c];
    size_t base; int stride;
    if (which == 0) { base = (size_t)b * BOFF + (size_t)idx * 256; stride = 24576; }
    else           { base = (size_t)b * BOFF + (size_t)idx * 24576; stride = 256; }

    float s = 0.f;
#pragma unroll 4
    for (int t = 0; t < 96; t++)
        s += X[base + (size_t)t * stride + c];
    red[c] = s * uv;
    __syncthreads();
#pragma unroll
    for (int o = 128; o; o >>= 1) {
        if (c < o) red[c] += red[c + o];
        __syncthreads();
    }
    if (c == 0) g_corr[which * 768 + r] = red[0];
}

// ============================================================================
// Kernel 2: logit partials (proven f32x2 version). grid (NSPLIT, 16).
// NSPLIT 64: lighter CTAs -> better last-wave fill (1024 CTAs vs 768).
// ============================================================================
__global__ __launch_bounds__(256, 3) void s_kernel(const float* __restrict__ X)
{
    __shared__ __align__(16) float As[32 * 98];
    __shared__ __align__(16) float Bs[32 * 98];

    const int split = blockIdx.x;
    const int mb    = blockIdx.y;
    const int mode  = mb >> 3;
    const int b     = mb & 7;

    const float* A = mode ? g_z : X;
    const float* B = mode ? X   : g_z;
    const int rowStride   = mode ? 24576 : 256;
    const int chunkStride = mode ? 256   : 24576;
    const size_t bbase = (size_t)b * BOFF;

    const int tid = threadIdx.x;
    const int tx = tid & 15, ty = tid >> 4;

    u64 acc[6][3];
#pragma unroll
    for (int i = 0; i < 6; i++)
#pragma unroll
        for (int j = 0; j < 3; j++) acc[i][j] = 0ULL;

#pragma unroll 1
    for (int kb = 0; kb < KSPLIT / 32; kb++) {
#pragma unroll
        for (int r = 0; r < 3; r++) {
            int f   = tid + 256 * r;
            int row = f >> 3;
            int k4  = f & 7;
            int kg0 = split * KSPLIT + kb * 32 + k4 * 4;
            int chunk = kg0 >> 8, cin = kg0 & 255;
            size_t ga = bbase + (size_t)row * rowStride + (size_t)chunk * chunkStride + cin;
            float4 a4 = *(const float4*)(A + ga);
            float4 b4 = *(const float4*)(B + ga);
            int ks = k4 * 4;
            As[(ks+0)*98 + row] = a4.x; As[(ks+1)*98 + row] = a4.y;
            As[(ks+2)*98 + row] = a4.z; As[(ks+3)*98 + row] = a4.w;
            Bs[(ks+0)*98 + row] = b4.x; Bs[(ks+1)*98 + row] = b4.y;
            Bs[(ks+2)*98 + row] = b4.z; Bs[(ks+3)*98 + row] = b4.w;
        }
        __syncthreads();
#pragma unroll 8
        for (int kk = 0; kk < 32; kk++) {
            u64 a[6], bv[3];
#pragma unroll
            for (int i = 0; i < 6; i++) a[i] = dup2(As[kk * 98 + ty * 6 + i]);
#pragma unroll
            for (int j = 0; j < 3; j++) bv[j] = *(const u64*)&Bs[kk * 98 + 6 * tx + 2 * j];
#pragma unroll
            for (int i = 0; i < 6; i++)
#pragma unroll
                for (int j = 0; j < 3; j++) ffma2(acc[i][j], a[i], bv[j]);
        }
        __syncthreads();
    }

    float* dst = g_Sp + (size_t)(split * 16 + mb) * PBATCH;
#pragma unroll
    for (int i = 0; i < 6; i++)
#pragma unroll
        for (int j = 0; j < 3; j++) {
            float2 r = unpack2(acc[i][j]);
            *(float2*)(dst + (ty * 6 + i) * 96 + 6 * tx + 2 * j) = r;
        }
}

// ============================================================================
// Kernel 3: softmax rows of 96 (sum NSPLIT partials + column correction).
// ============================================================================
__global__ __launch_bounds__(32) void softmax_kernel()
{
    const int rowid = blockIdx.x;
    const int mb = rowid / 96, i = rowid - mb * 96;
    const int mode = mb >> 3, b = mb & 7;
    const int t = threadIdx.x;
    const float* corr = g_corr + mode * 768 + b * 96;

    float v[3];
#pragma unroll
    for (int u = 0; u < 3; u++) {
        int j = t + 32 * u;
        float s = corr[j];
#pragma unroll 8
        for (int sp = 0; sp < NSPLIT; sp++)
            s += g_Sp[(size_t)(sp * 16 + mb) * PBATCH + i * 96 + j];
        v[u] = s;
    }
    float mx = fmaxf(v[0], fmaxf(v[1], v[2]));
#pragma unroll
    for (int o = 16; o; o >>= 1) mx = fmaxf(mx, __shfl_xor_sync(0xffffffffu, mx, o));
    float sum = 0.f;
#pragma unroll
    for (int u = 0; u < 3; u++) { v[u] = expf(v[u] - mx); sum += v[u]; }
#pragma unroll
    for (int o = 16; o; o >>= 1) sum += __shfl_xor_sync(0xffffffffu, sum, o);
    float inv = 1.f / sum;
#pragma unroll
    for (int u = 0; u < 3; u++)
        g_P[mb * PBATCH + i * 96 + t + 32 * u] = v[u] * inv;
}

// ============================================================================
// Kernels 4/5: O_tile(96x128) = P(96x96) * V(96x128). grid (768, 2).
// (proven f32x2 version, unchanged)
// ============================================================================
#define PV_PS   (96 * 97)
#define PV_VS   (16 * 132)
#define PV_SMEM ((PV_PS + 2 * PV_VS) * 4)

__global__ __launch_bounds__(256, 3) void pv_kernel(float* __restrict__ out, int mode_ma)
{
    extern __shared__ __align__(16) float dsm[];
    float* Ps = dsm;
    float* Vs = dsm + PV_PS;

    const int s = blockIdx.x;
    const int ct = blockIdx.y;
    const int b = s / 96, idx = s - b * 96;
    const int c0 = ct * 128;

    size_t vbase, outBase; int vStride, outStride, pBase;
    if (mode_ma) {
        vbase   = (size_t)b * BOFF + (size_t)idx * 256;   vStride = 24576;
        outBase = (size_t)b * BOFF + (size_t)idx * 256;   outStride = 24576;
        pBase = (8 + b) * PBATCH;
    } else {
        vbase   = (size_t)b * BOFF + (size_t)idx * 24576; vStride = 256;
        outBase = (size_t)b * BOFF + (size_t)idx * 24576; outStride = 256;
        pBase = b * PBATCH;
    }

    const int tid = threadIdx.x;
    const int tx = tid & 15, ty = tid >> 4;

    for (int f = tid; f < 96 * 96; f += 256) {
        int r = f / 96, k = f - r * 96;
        Ps[r * 97 + k] = g_P[pBase + f];
    }

    const int vrow  = tid >> 5;
    const int vcolq = tid & 31;
    float4 vr[2];
#pragma unroll
    for (int r2 = 0; r2 < 2; r2++)
        vr[r2] = *(const float4*)(g_v + vbase + (size_t)(vrow + 8 * r2) * vStride + c0 + vcolq * 4);
#pragma unroll
    for (int r2 = 0; r2 < 2; r2++)
        *(float4*)&Vs[(vrow + 8 * r2) * 132 + vcolq * 4] = vr[r2];
    __syncthreads();

    u64 acc[6][4];
#pragma unroll
    for (int i = 0; i < 6; i++)
#pragma unroll
        for (int j = 0; j < 4; j++) acc[i][j] = 0ULL;

#pragma unroll 1
    for (int kb = 0; kb < 6; kb++) {
        const int buf = kb & 1;
        if (kb < 5) {
#pragma unroll
            for (int r2 = 0; r2 < 2; r2++)
                vr[r2] = *(const float4*)(g_v + vbase +
                    (size_t)((kb + 1) * 16 + vrow + 8 * r2) * vStride + c0 + vcolq * 4);
        }
        const float* Vb = Vs + buf * PV_VS;
#pragma unroll
        for (int kk = 0; kk < 16; kk++) {
            int kg = kb * 16 + kk;
            u64 a[6], bv[4];
#pragma unroll
            for (int i = 0; i < 6; i++) a[i] = dup2(Ps[(ty * 6 + i) * 97 + kg]);
#pragma unroll
            for (int j = 0; j < 4; j++) bv[j] = *(const u64*)&Vb[kk * 132 + 2 * tx + 32 * j];
#pragma unroll
            for (int i = 0; i < 6; i++)
#pragma unroll
                for (int j = 0; j < 4; j++) ffma2(acc[i][j], a[i], bv[j]);
        }
        if (kb < 5) {
            float* Vn = Vs + (buf ^ 1) * PV_VS;
#pragma unroll
            for (int r2 = 0; r2 < 2; r2++)
                *(float4*)&Vn[(vrow + 8 * r2) * 132 + vcolq * 4] = vr[r2];
            __syncthreads();
        }
    }

#pragma unroll
    for (int i = 0; i < 6; i++)
#pragma unroll
        for (int j = 0; j < 4; j++) {
            float2 r = unpack2(acc[i][j]);
            size_t addr = outBase + (size_t)(ty * 6 + i) * outStride + c0 + 2 * tx + 32 * j;
            if (mode_ma) {
                *(float2*)(out + addr) = r;
            } else {
                float2 o = *(const float2*)(out + addr);
                o.x += r.x; o.y += r.y;
                *(float2*)(out + addr) = o;
            }
        }
}

// ============================================================================
extern "C" void kernel_launch(void* const* d_in, const int* in_sizes, int n_in,
                              void* d_out, int out_size) {
    const float* x    = (const float*)d_in[0];
    const float* w    = (const float*)d_in[1];
    const float* bias = (const float*)d_in[2];
    float* out = (float*)d_out;

    static int attr_done = 0;
    if (!attr_done) {
        cudaFuncSetAttribute(gemm_kernel, cudaFuncAttributeMaxDynamicSharedMemorySize, GT_SMEM);
        cudaFuncSetAttribute(pv_kernel,   cudaFuncAttributeMaxDynamicSharedMemorySize, PV_SMEM);
        attr_done = 1;
    }

    prep_kernel<<<514, 256>>>(w, bias);
    gemm_kernel<<<dim3(8, 576), 256, GT_SMEM>>>(x, bias);
    corr_kernel<<<1536, 256>>>(x);
    s_kernel<<<dim3(NSPLIT, 16), 256>>>(x);
    softmax_kernel<<<16 * 96, 32>>>();
    pv_kernel<<<dim3(768, 2), 256, PV_SMEM>>>(out, 1);  // ma: full overwrite
    pv_kernel<<<dim3(768, 2), 256, PV_SMEM>>>(out, 0);  // ms: accumulate
}

// round 17
// speedup vs baseline: 1.0703x; 1.0703x over previous
#include <cuda_runtime.h>
#include <cstdint>

typedef unsigned long long u64;

#define NB 8
#define WD 96
#define HD 96
#define CD 256
#define PBATCH (WD*HD)            /* 9216 */
#define BOFF (PBATCH*CD)          /* 2359296 floats per batch */
#define ARRN (NB*BOFF)            /* 18874368 */
#define NSPLIT 64
#define KSPLIT 384                /* 24576 / NSPLIT, multiple of 32 */

// ---------------- device scratch ----------------
__device__ float g_z[ARRN];                   // z = G x, p-major [b][w][h][c]
__device__ float g_v[ARRN];                   // v, p-major
__device__ float g_Sp[NSPLIT * 16 * PBATCH];  // [split][mode*8+b][96][96]
__device__ float g_P[16 * PBATCH];            // softmaxed probs
__device__ float g_wchi[512 * 256];           // [G ; Wv] hi (tf32)
__device__ float g_wclo[512 * 256];           // [G ; Wv] lo residual (tf32)
__device__ float g_u[256];                    // Wq^T bk
__device__ float g_u2[256];                   // Wk^T bq
__device__ float g_corr[2 * 768];             // [Cms ; Cma] col corrections

// ---------------- f32x2 helpers ----------------
__device__ __forceinline__ void ffma2(u64 &d, u64 a, u64 b) {
    asm("fma.rn.f32x2 %0, %1, %2, %0;" : "+l"(d) : "l"(a), "l"(b));
}
__device__ __forceinline__ u64 dup2(float x) {
    u64 r; asm("mov.b64 %0, {%1, %1};" : "=l"(r) : "f"(x)); return r;
}
__device__ __forceinline__ float2 unpack2(u64 v) {
    float2 f; asm("mov.b64 {%0, %1}, %2;" : "=f"(f.x), "=f"(f.y) : "l"(v)); return f;
}

// ---------------- tf32 mma helpers ----------------
__device__ __forceinline__ uint32_t tf32cvt(float x) {
    uint32_t u; asm("cvt.rna.tf32.f32 %0, %1;" : "=r"(u) : "f"(x)); return u;
}
__device__ __forceinline__ float tf32f(float x) {
    return __uint_as_float(tf32cvt(x));
}
__device__ __forceinline__ void mma1688(float* c, const uint32_t* a, const uint32_t* b) {
    asm volatile("mma.sync.aligned.m16n8k8.row.col.f32.tf32.tf32.f32 "
        "{%0,%1,%2,%3}, {%4,%5,%6,%7}, {%8,%9}, {%0,%1,%2,%3};"
        : "+f"(c[0]), "+f"(c[1]), "+f"(c[2]), "+f"(c[3])
        : "r"(a[0]), "r"(a[1]), "r"(a[2]), "r"(a[3]), "r"(b[0]), "r"(b[1]));
}

// ============================================================================
// Kernel 0: prep. Blocks 0..255: G row -> hi/lo split. 256..511: Wv -> hi/lo.
// Block 512: u. Block 513: u2.
// ============================================================================
__global__ __launch_bounds__(256) void prep_kernel(
    const float* __restrict__ W, const float* __restrict__ bias)
{
    const int blk = blockIdx.x;
    const int c = threadIdx.x;
    if (blk < 256) {
        __shared__ float sWq[256];
        sWq[c] = W[c * 256 + blk];          // Wq[t=c][o=blk]
        __syncthreads();
        float acc = 0.f;
#pragma unroll 4
        for (int t = 0; t < 256; t++)
            acc += sWq[t] * W[(256 + t) * 256 + c];   // Wk[t][c]
        float hi = tf32f(acc);
        g_wchi[blk * 256 + c] = hi;
        g_wclo[blk * 256 + c] = tf32f(acc - hi);
    } else if (blk < 512) {
        int o = blk - 256;
        float wv = W[(512 + o) * 256 + c];
        float hi = tf32f(wv);
        g_wchi[(256 + o) * 256 + c] = hi;
        g_wclo[(256 + o) * 256 + c] = tf32f(wv - hi);
    } else if (blk == 512) {
        float acc = 0.f;
#pragma unroll 4
        for (int t = 0; t < 256; t++)
            acc += W[t * 256 + c] * bias[256 + t];
        g_u[c] = acc;
    } else {
        float acc = 0.f;
#pragma unroll 4
        for (int t = 0; t < 256; t++)
            acc += W[(256 + t) * 256 + c] * bias[t];
        g_u2[c] = acc;
    }
}

// ============================================================================
// Kernel 1: main GEMM on tensor cores (tf32 split) — r14 proven config.
// z half (n0<256): 3 passes. v half: 2 passes. launch_bounds (256,2): NO spills.
// Grid (8 n-blocks, 576 m-blocks): n fastest -> X tile L2-reused, W resident.
// ============================================================================
#define GT_STR 20
#define GT_A   (128 * GT_STR)
#define GT_B   (64 * GT_STR)
#define GT_SMEM (2 * (2 * GT_A + 2 * GT_B) * 4)   /* 61440 B */

__global__ __launch_bounds__(256, 2) void gemm_kernel(
    const float* __restrict__ X, const float* __restrict__ bias)
{
    extern __shared__ __align__(16) uint32_t gts[];
    uint32_t* Ahi = gts;
    uint32_t* Alo = gts + 2 * GT_A;
    uint32_t* Bhi = gts + 4 * GT_A;
    uint32_t* Blo = gts + 4 * GT_A + 2 * GT_B;

    const int tid  = threadIdx.x;
    const int lane = tid & 31, wid = tid >> 5;
    const int wm = wid & 3, wn = wid >> 2;
    const int n0 = blockIdx.x * 64;
    const int m0 = blockIdx.y * 128;
    const int isv = (n0 >= 256);

    const float* Ag  = X      + (size_t)m0 * CD;
    const float* Bgh = g_wchi + (size_t)n0 * CD;
    const float* Bgl = g_wclo + (size_t)n0 * CD;

    const int srow = tid >> 2;
    const int c4   = tid & 3;

    float acc[2][4][4];
#pragma unroll
    for (int tm = 0; tm < 2; tm++)
#pragma unroll
        for (int tn = 0; tn < 4; tn++)
#pragma unroll
            for (int q = 0; q < 4; q++) acc[tm][tn][q] = 0.f;

    float4 ra[2], rbh, rbl;
    ra[0] = *(const float4*)(Ag + (size_t)srow * CD + c4 * 4);
    ra[1] = *(const float4*)(Ag + (size_t)(srow + 64) * CD + c4 * 4);
    rbh   = *(const float4*)(Bgh + (size_t)srow * CD + c4 * 4);
    if (!isv) rbl = *(const float4*)(Bgl + (size_t)srow * CD + c4 * 4);
    {
#pragma unroll
        for (int it = 0; it < 2; it++) {
            const float* pa = (const float*)&ra[it];
            uint4 h, l;
            uint32_t* hp = (uint32_t*)&h; uint32_t* lp = (uint32_t*)&l;
#pragma unroll
            for (int u = 0; u < 4; u++) {
                uint32_t hb = tf32cvt(pa[u]);
                hp[u] = hb;
                lp[u] = tf32cvt(pa[u] - __uint_as_float(hb));
            }
            int off = (srow + 64 * it) * GT_STR + c4 * 4;
            *(uint4*)&Ahi[off] = h;
            *(uint4*)&Alo[off] = l;
        }
        int off = srow * GT_STR + c4 * 4;
        *(uint4*)&Bhi[off] = *(const uint4*)&rbh;
        if (!isv) *(uint4*)&Blo[off] = *(const uint4*)&rbl;
    }
    __syncthreads();

#pragma unroll 1
    for (int s = 0; s < 16; s++) {
        const int buf = s & 1;
        if (s < 15) {
            int ks = (s + 1) * 16;
            ra[0] = *(const float4*)(Ag + (size_t)srow * CD + ks + c4 * 4);
            ra[1] = *(const float4*)(Ag + (size_t)(srow + 64) * CD + ks + c4 * 4);
            rbh   = *(const float4*)(Bgh + (size_t)srow * CD + ks + c4 * 4);
            if (!isv) rbl = *(const float4*)(Bgl + (size_t)srow * CD + ks + c4 * 4);
        }
        const uint32_t* Abh = Ahi + buf * GT_A;
        const uint32_t* Abl = Alo + buf * GT_A;
        const uint32_t* Bbh = Bhi + buf * GT_B;
        const uint32_t* Bbl = Blo + buf * GT_B;
#pragma unroll
        for (int g = 0; g < 2; g++) {
            uint32_t ah[2][4], al[2][4];
#pragma unroll
            for (int tm = 0; tm < 2; tm++)
#pragma unroll
                for (int q = 0; q < 4; q++) {
                    int r = 32 * wm + 16 * tm + (lane >> 2) + 8 * (q & 1);
                    int c = 8 * g + (lane & 3) + 4 * (q >> 1);
                    ah[tm][q] = Abh[r * GT_STR + c];
                    al[tm][q] = Abl[r * GT_STR + c];
                }
            uint32_t bh[4][2], bl[4][2];
#pragma unroll
            for (int tn = 0; tn < 4; tn++)
#pragma unroll
                for (int q = 0; q < 2; q++) {
                    int n = 32 * wn + 8 * tn + (lane >> 2);
                    int k = 8 * g + (lane & 3) + 4 * q;
                    bh[tn][q] = Bbh[n * GT_STR + k];
                    if (!isv) bl[tn][q] = Bbl[n * GT_STR + k];
                }
#pragma unroll
            for (int tm = 0; tm < 2; tm++)
#pragma unroll
                for (int tn = 0; tn < 4; tn++) {
                    mma1688(acc[tm][tn], ah[tm], bh[tn]);
                    mma1688(acc[tm][tn], al[tm], bh[tn]);
                    if (!isv) mma1688(acc[tm][tn], ah[tm], bl[tn]);
                }
        }
        if (s < 15) {
            const int nbuf = buf ^ 1;
            uint32_t* Anh = Ahi + nbuf * GT_A;
            uint32_t* Anl = Alo + nbuf * GT_A;
#pragma unroll
            for (int it = 0; it < 2; it++) {
                const float* pa = (const float*)&ra[it];
                uint4 h, l;
                uint32_t* hp = (uint32_t*)&h; uint32_t* lp = (uint32_t*)&l;
#pragma unroll
                for (int u = 0; u < 4; u++) {
                    uint32_t hb = tf32cvt(pa[u]);
                    hp[u] = hb;
                    lp[u] = tf32cvt(pa[u] - __uint_as_float(hb));
                }
                int off = (srow + 64 * it) * GT_STR + c4 * 4;
                *(uint4*)&Anh[off] = h;
                *(uint4*)&Anl[off] = l;
            }
            int off = srow * GT_STR + c4 * 4;
            *(uint4*)&Bhi[nbuf * GT_B + off] = *(const uint4*)&rbh;
            if (!isv) *(uint4*)&Blo[nbuf * GT_B + off] = *(const uint4*)&rbl;
            __syncthreads();
        }
    }

    // epilogue: p-major store; bias only for v half
    const int cbase = n0 & 255;
    float* dst = isv ? g_v : g_z;
#pragma unroll
    for (int tm = 0; tm < 2; tm++)
#pragma unroll
        for (int tn = 0; tn < 4; tn++)
#pragma unroll
            for (int half = 0; half < 2; half++) {
                int p  = m0 + 32 * wm + 16 * tm + (lane >> 2) + 8 * half;
                int cl = cbase + 32 * wn + 8 * tn + 2 * (lane & 3);
                float2 r = make_float2(acc[tm][tn][2 * half], acc[tm][tn][2 * half + 1]);
                if (isv) {
                    float2 bv = *(const float2*)(bias + 512 + cl);
                    r.x += bv.x; r.y += bv.y;
                }
                *(float2*)(dst + (size_t)p * CD + cl) = r;
            }
}

// ============================================================================
// Kernel 1b: column corrections. (unchanged)
// ============================================================================
__global__ __launch_bounds__(256) void corr_kernel(const float* __restrict__ X)
{
    __shared__ float red[256];
    const int id = blockIdx.x;
    const int which = id / 768;
    const int r = id - which * 768;
    const int b = r / 96, idx = r - b * 96;
    const int c = threadIdx.x;

    const float uv = which ? g_u[c] : g_u2[c];
    size_t base; int stride;
    if (which == 0) { base = (size_t)b * BOFF + (size_t)idx * 256; stride = 24576; }
    else           { base = (size_t)b * BOFF + (size_t)idx * 24576; stride = 256; }

    float s = 0.f;
#pragma unroll 4
    for (int t = 0; t < 96; t++)
        s += X[base + (size_t)t * stride + c];
    red[c] = s * uv;
    __syncthreads();
#pragma unroll
    for (int o = 128; o; o >>= 1) {
        if (c < o) red[c] += red[c + o];
        __syncthreads();
    }
    if (c == 0) g_corr[which * 768 + r] = red[0];
}

// ============================================================================
// Kernel 2: logit partials (proven f32x2 version). grid (NSPLIT, 16).
// NSPLIT 64: measured 164us (was 182 at 48).
// ============================================================================
__global__ __launch_bounds__(256, 3) void s_kernel(const float* __restrict__ X)
{
    __shared__ __align__(16) float As[32 * 98];
    __shared__ __align__(16) float Bs[32 * 98];

    const int split = blockIdx.x;
    const int mb    = blockIdx.y;
    const int mode  = mb >> 3;
    const int b     = mb & 7;

    const float* A = mode ? g_z : X;
    const float* B = mode ? X   : g_z;
    const int rowStride   = mode ? 24576 : 256;
    const int chunkStride = mode ? 256   : 24576;
    const size_t bbase = (size_t)b * BOFF;

    const int tid = threadIdx.x;
    const int tx = tid & 15, ty = tid >> 4;

    u64 acc[6][3];
#pragma unroll
    for (int i = 0; i < 6; i++)
#pragma unroll
        for (int j = 0; j < 3; j++) acc[i][j] = 0ULL;

#pragma unroll 1
    for (int kb = 0; kb < KSPLIT / 32; kb++) {
#pragma unroll
        for (int r = 0; r < 3; r++) {
            int f   = tid + 256 * r;
            int row = f >> 3;
            int k4  = f & 7;
            int kg0 = split * KSPLIT + kb * 32 + k4 * 4;
            int chunk = kg0 >> 8, cin = kg0 & 255;
            size_t ga = bbase + (size_t)row * rowStride + (size_t)chunk * chunkStride + cin;
            float4 a4 = *(const float4*)(A + ga);
            float4 b4 = *(const float4*)(B + ga);
            int ks = k4 * 4;
            As[(ks+0)*98 + row] = a4.x; As[(ks+1)*98 + row] = a4.y;
            As[(ks+2)*98 + row] = a4.z; As[(ks+3)*98 + row] = a4.w;
            Bs[(ks+0)*98 + row] = b4.x; Bs[(ks+1)*98 + row] = b4.y;
            Bs[(ks+2)*98 + row] = b4.z; Bs[(ks+3)*98 + row] = b4.w;
        }
        __syncthreads();
#pragma unroll 8
        for (int kk = 0; kk < 32; kk++) {
            u64 a[6], bv[3];
#pragma unroll
            for (int i = 0; i < 6; i++) a[i] = dup2(As[kk * 98 + ty * 6 + i]);
#pragma unroll
            for (int j = 0; j < 3; j++) bv[j] = *(const u64*)&Bs[kk * 98 + 6 * tx + 2 * j];
#pragma unroll
            for (int i = 0; i < 6; i++)
#pragma unroll
                for (int j = 0; j < 3; j++) ffma2(acc[i][j], a[i], bv[j]);
        }
        __syncthreads();
    }

    float* dst = g_Sp + (size_t)(split * 16 + mb) * PBATCH;
#pragma unroll
    for (int i = 0; i < 6; i++)
#pragma unroll
        for (int j = 0; j < 3; j++) {
            float2 r = unpack2(acc[i][j]);
            *(float2*)(dst + (ty * 6 + i) * 96 + 6 * tx + 2 * j) = r;
        }
}

// ============================================================================
// Kernel 3: softmax rows of 96 (sum NSPLIT partials + column correction).
// ============================================================================
__global__ __launch_bounds__(32) void softmax_kernel()
{
    const int rowid = blockIdx.x;
    const int mb = rowid / 96, i = rowid - mb * 96;
    const int mode = mb >> 3, b = mb & 7;
    const int t = threadIdx.x;
    const float* corr = g_corr + mode * 768 + b * 96;

    float v[3];
#pragma unroll
    for (int u = 0; u < 3; u++) {
        int j = t + 32 * u;
        float s = corr[j];
#pragma unroll 8
        for (int sp = 0; sp < NSPLIT; sp++)
            s += g_Sp[(size_t)(sp * 16 + mb) * PBATCH + i * 96 + j];
        v[u] = s;
    }
    float mx = fmaxf(v[0], fmaxf(v[1], v[2]));
#pragma unroll
    for (int o = 16; o; o >>= 1) mx = fmaxf(mx, __shfl_xor_sync(0xffffffffu, mx, o));
    float sum = 0.f;
#pragma unroll
    for (int u = 0; u < 3; u++) { v[u] = expf(v[u] - mx); sum += v[u]; }
#pragma unroll
    for (int o = 16; o; o >>= 1) sum += __shfl_xor_sync(0xffffffffu, sum, o);
    float inv = 1.f / sum;
#pragma unroll
    for (int u = 0; u < 3; u++)
        g_P[mb * PBATCH + i * 96 + t + 32 * u] = v[u] * inv;
}

// ============================================================================
// Kernels 4/5: O_tile(96x128) = P(96x96) * V(96x128). grid (768, 2).
// (proven f32x2 version, unchanged)
// ============================================================================
#define PV_PS   (96 * 97)
#define PV_VS   (16 * 132)
#define PV_SMEM ((PV_PS + 2 * PV_VS) * 4)

__global__ __launch_bounds__(256, 3) void pv_kernel(float* __restrict__ out, int mode_ma)
{
    extern __shared__ __align__(16) float dsm[];
    float* Ps = dsm;
    float* Vs = dsm + PV_PS;

    const int s = blockIdx.x;
    const int ct = blockIdx.y;
    const int b = s / 96, idx = s - b * 96;
    const int c0 = ct * 128;

    size_t vbase, outBase; int vStride, outStride, pBase;
    if (mode_ma) {
        vbase   = (size_t)b * BOFF + (size_t)idx * 256;   vStride = 24576;
        outBase = (size_t)b * BOFF + (size_t)idx * 256;   outStride = 24576;
        pBase = (8 + b) * PBATCH;
    } else {
        vbase   = (size_t)b * BOFF + (size_t)idx * 24576; vStride = 256;
        outBase = (size_t)b * BOFF + (size_t)idx * 24576; outStride = 256;
        pBase = b * PBATCH;
    }

    const int tid = threadIdx.x;
    const int tx = tid & 15, ty = tid >> 4;

    for (int f = tid; f < 96 * 96; f += 256) {
        int r = f / 96, k = f - r * 96;
        Ps[r * 97 + k] = g_P[pBase + f];
    }

    const int vrow  = tid >> 5;
    const int vcolq = tid & 31;
    float4 vr[2];
#pragma unroll
    for (int r2 = 0; r2 < 2; r2++)
        vr[r2] = *(const float4*)(g_v + vbase + (size_t)(vrow + 8 * r2) * vStride + c0 + vcolq * 4);
#pragma unroll
    for (int r2 = 0; r2 < 2; r2++)
        *(float4*)&Vs[(vrow + 8 * r2) * 132 + vcolq * 4] = vr[r2];
    __syncthreads();

    u64 acc[6][4];
#pragma unroll
    for (int i = 0; i < 6; i++)
#pragma unroll
        for (int j = 0; j < 4; j++) acc[i][j] = 0ULL;

#pragma unroll 1
    for (int kb = 0; kb < 6; kb++) {
        const int buf = kb & 1;
        if (kb < 5) {
#pragma unroll
            for (int r2 = 0; r2 < 2; r2++)
                vr[r2] = *(const float4*)(g_v + vbase +
                    (size_t)((kb + 1) * 16 + vrow + 8 * r2) * vStride + c0 + vcolq * 4);
        }
        const float* Vb = Vs + buf * PV_VS;
#pragma unroll
        for (int kk = 0; kk < 16; kk++) {
            int kg = kb * 16 + kk;
            u64 a[6], bv[4];
#pragma unroll
            for (int i = 0; i < 6; i++) a[i] = dup2(Ps[(ty * 6 + i) * 97 + kg]);
#pragma unroll
            for (int j = 0; j < 4; j++) bv[j] = *(const u64*)&Vb[kk * 132 + 2 * tx + 32 * j];
#pragma unroll
            for (int i = 0; i < 6; i++)
#pragma unroll
                for (int j = 0; j < 4; j++) ffma2(acc[i][j], a[i], bv[j]);
        }
        if (kb < 5) {
            float* Vn = Vs + (buf ^ 1) * PV_VS;
#pragma unroll
            for (int r2 = 0; r2 < 2; r2++)
                *(float4*)&Vn[(vrow + 8 * r2) * 132 + vcolq * 4] = vr[r2];
            __syncthreads();
        }
    }

#pragma unroll
    for (int i = 0; i < 6; i++)
#pragma unroll
        for (int j = 0; j < 4; j++) {
            float2 r = unpack2(acc[i][j]);
            size_t addr = outBase + (size_t)(ty * 6 + i) * outStride + c0 + 2 * tx + 32 * j;
            if (mode_ma) {
                *(float2*)(out + addr) = r;
            } else {
                float2 o = *(const float2*)(out + addr);
                o.x += r.x; o.y += r.y;
                *(float2*)(out + addr) = o;
            }
        }
}

// ============================================================================
extern "C" void kernel_launch(void* const* d_in, const int* in_sizes, int n_in,
                              void* d_out, int out_size) {
    const float* x    = (const float*)d_in[0];
    const float* w    = (const float*)d_in[1];
    const float* bias = (const float*)d_in[2];
    float* out = (float*)d_out;

    static int attr_done = 0;
    if (!attr_done) {
        cudaFuncSetAttribute(gemm_kernel, cudaFuncAttributeMaxDynamicSharedMemorySize, GT_SMEM);
        cudaFuncSetAttribute(pv_kernel,   cudaFuncAttributeMaxDynamicSharedMemorySize, PV_SMEM);
        attr_done = 1;
    }

    prep_kernel<<<514, 256>>>(w, bias);
    gemm_kernel<<<dim3(8, 576), 256, GT_SMEM>>>(x, bias);
    corr_kernel<<<1536, 256>>>(x);
    s_kernel<<<dim3(NSPLIT, 16), 256>>>(x);
    softmax_kernel<<<16 * 96, 32>>>();
    pv_kernel<<<dim3(768, 2), 256, PV_SMEM>>>(out, 1);  // ma: full overwrite
    pv_kernel<<<dim3(768, 2), 256, PV_SMEM>>>(out, 0);  // ms: accumulate
}